// round 13
// baseline (speedup 1.0000x reference)
#include <cuda_runtime.h>
#include <cuda_bf16.h>
#include <cstdint>
#include <cstddef>

#define NODES_MAX 100000
#define EDGES_MAX 1600000
#define DD 128

// ---------------------------------------------------------------------------
// Static device scratch
// ---------------------------------------------------------------------------
__device__ float g_bufA[(size_t)NODES_MAX * DD];   // m (x @ W)
__device__ float g_bufB[(size_t)NODES_MAX * DD];   // res
__device__ float g_bufC[(size_t)NODES_MAX * DD];   // y1
__device__ float g_bufD[(size_t)NODES_MAX * DD];   // y2
__device__ float g_stats[2 * DD];
__device__ float g_c0[DD];
__device__ float g_br1p[DD];
__device__ int   g_rowptr[NODES_MAX + 1];
__device__ int   g_cursor[NODES_MAX];   // deg histogram, then fill cursor
__device__ int   g_esrc[EDGES_MAX];
__device__ int   g_bsum[128];
// 4 weight images (W0, Wr0, W1p, Wr1p): transposed [n][k] bf16, hi then lo
__device__ __nv_bfloat16 g_wimg[4][32768];

// ---------------------------------------------------------------------------
// mma.sync / ldmatrix helpers (target-portable PTX, no 'a'-suffix features)
// ---------------------------------------------------------------------------
__device__ __forceinline__ uint32_t smem_to_u32(const void* p) {
    uint32_t a;
    asm("{ .reg .u64 t; cvta.to.shared.u64 t, %1; cvt.u32.u64 %0, t; }"
        : "=r"(a) : "l"(p));
    return a;
}

#define LDSM_X4(r0, r1, r2, r3, addr) \
    asm volatile("ldmatrix.sync.aligned.m8n8.x4.shared.b16 {%0,%1,%2,%3}, [%4];" \
                 : "=r"(r0), "=r"(r1), "=r"(r2), "=r"(r3) : "r"(addr))

__device__ __forceinline__ void mma16816(float* c, const uint32_t* a,
                                         const uint32_t* b) {
    asm volatile(
        "mma.sync.aligned.m16n8k16.row.col.f32.bf16.bf16.f32 "
        "{%0,%1,%2,%3}, {%4,%5,%6,%7}, {%8,%9}, {%0,%1,%2,%3};"
        : "+f"(c[0]), "+f"(c[1]), "+f"(c[2]), "+f"(c[3])
        : "r"(a[0]), "r"(a[1]), "r"(a[2]), "r"(a[3]), "r"(b[0]), "r"(b[1]));
}

// packed fp32 pair add (proven on this toolchain since R2)
__device__ __forceinline__ void addf32x2(unsigned long long& d,
                                         unsigned long long a) {
    asm("add.rn.f32x2 %0, %0, %1;" : "+l"(d) : "l"(a));
}

__device__ __forceinline__ void split_store(__nv_bfloat16* img, int n, int k, float w)
{
    __nv_bfloat16 hi = __float2bfloat16_rn(w);
    img[n * 128 + k] = hi;
    img[16384 + n * 128 + k] = __float2bfloat16_rn(w - __bfloat162float(hi));
}

// ---------------------------------------------------------------------------
// Layer-1 weight prep: both W0 and Wr0 in one launch (grid 256)
// ---------------------------------------------------------------------------
__global__ void prep_pair_kernel(const float* __restrict__ Wa,
                                 const float* __restrict__ Wb,
                                 __nv_bfloat16* __restrict__ imga,
                                 __nv_bfloat16* __restrict__ imgb)
{
    int b = blockIdx.x;
    const float* W = (b < 128) ? Wa : Wb;
    __nv_bfloat16* img = (b < 128) ? imga : imgb;
    int n = b & 127;
    int k = threadIdx.x;
    split_store(img, n, k, W[k * 128 + n]);
}

// ---------------------------------------------------------------------------
// Layer-2 prep megakernel (BN fold into weights/biases), grid 258 x 128
// ---------------------------------------------------------------------------
__global__ void l2prep_kernel(const float* __restrict__ stats,
                              const float* __restrict__ g,
                              const float* __restrict__ be,
                              float invN,
                              const float* __restrict__ W1,
                              const float* __restrict__ Wr1,
                              const float* __restrict__ br1,
                              __nv_bfloat16* __restrict__ img2,
                              __nv_bfloat16* __restrict__ img3,
                              float* __restrict__ c0,
                              float* __restrict__ br1p)
{
    int b = blockIdx.x;
    int t = threadIdx.x;
    float mu = stats[t] * invN;
    float var = stats[128 + t] * invN - mu * mu;
    float sc = rsqrtf(var + 1e-5f) * g[t];
    float sf = be[t] - mu * sc;

    if (b < 256) {
        const float* W = (b < 128) ? W1 : Wr1;
        __nv_bfloat16* img = (b < 128) ? img2 : img3;
        int n = b & 127;
        split_store(img, n, t, W[t * 128 + n] * sc);
    } else {
        __shared__ float sh[128];
        sh[t] = sf;
        __syncthreads();
        const float* W = (b == 256) ? W1 : Wr1;
        float s = (b == 256) ? 0.f : br1[t];
        for (int k = 0; k < 128; k++) s += sh[k] * W[k * 128 + t];
        if (b == 256) c0[t] = s;
        else          br1p[t] = s;
    }
}

// ---------------------------------------------------------------------------
// PERSISTENT fused GEMM pair via mma.sync bf16 3-term split:
//   outM = A @ W ; outR = relu(A @ Wr + br)
// grid = 148 (1 CTA/SM), B tiles loaded ONCE per CTA, loop over row tiles.
// B hi+lo fragments fetched in a single ldmatrix.x4 (lanes>=16 -> lo image).
// Block 0 also zeroes stats for the following gather.
// ---------------------------------------------------------------------------
#define RS      272u
#define SM_AHI  0u
#define SM_ALO  34816u
#define SM_BHI  69632u
#define SM_BLO  139264u
#define SMEM_GP 208896u

__device__ __forceinline__ void cvt_pair(float a, float b, char* phi, char* plo)
{
    __nv_bfloat16 ha = __float2bfloat16_rn(a);
    __nv_bfloat16 hb = __float2bfloat16_rn(b);
    *(__nv_bfloat162*)phi = __halves2bfloat162(ha, hb);
    *(__nv_bfloat162*)plo = __halves2bfloat162(
        __float2bfloat16_rn(a - __bfloat162float(ha)),
        __float2bfloat16_rn(b - __bfloat162float(hb)));
}

__global__ __launch_bounds__(512, 1) void gemm_pair_kernel(
    const float* __restrict__ A,
    const __nv_bfloat16* __restrict__ imgW,
    const __nv_bfloat16* __restrict__ imgR,
    const float* __restrict__ br,
    float* __restrict__ outM, float* __restrict__ outR,
    float* __restrict__ stats, int M, int nTiles)
{
    extern __shared__ char sm[];
    const uint32_t smb = smem_to_u32(sm);
    const int tid = threadIdx.x;
    const int warp = tid >> 5;
    const int lane = tid & 31;

    if (blockIdx.x == 0 && tid < 256) stats[tid] = 0.f;

    // ---- B tiles: load ONCE (rows 0-127: W^T, 128-255: Wr^T) ----
    for (int i = tid; i < 4096; i += 512) {
        int row = i >> 4, q = i & 15;
        const __nv_bfloat16* srcb = (row < 128) ? imgW : imgR;
        int r = row & 127;
        uint4 vhi = ((const uint4*)(srcb + r * 128))[q];
        uint4 vlo = ((const uint4*)(srcb + 16384 + r * 128))[q];
        *(uint4*)(sm + SM_BHI + row * RS + q * 16) = vhi;
        *(uint4*)(sm + SM_BLO + row * RS + q * 16) = vlo;
    }

    const int wm = warp >> 3;
    const int wn = warp & 7;
    const bool isRes = (wn >= 4);
    const int colb = wn * 32 - (isRes ? 128 : 0);

    const uint32_t a_addr0 = smb + SM_AHI
        + (uint32_t)(wm * 64 + (lane & 15)) * RS + (uint32_t)((lane >> 4) & 1) * 16u;
    // B x4 address: lanes 0-15 -> hi image (matrices 0,1), lanes 16-31 -> lo
    // image at the same row/col (matrices 2,3). One LDSM_X4 = bhi+blo frags.
    const uint32_t b_addr0 = smb + SM_BHI
        + (uint32_t)(wn * 32 + (lane & 7)) * RS + (uint32_t)((lane >> 3) & 1) * 16u
        + ((lane >= 16) ? (SM_BLO - SM_BHI) : 0u);

    // epilogue bias regs (loop-invariant)
    float q0[4], q1[4];
    if (isRes) {
#pragma unroll
        for (int nt = 0; nt < 4; nt++) {
            int col = colb + nt * 8 + (lane & 3) * 2;
            q0[nt] = __ldg(br + col);
            q1[nt] = __ldg(br + col + 1);
        }
    }

    // ---- Persistent loop over row tiles ----
    for (int t = blockIdx.x; t < nTiles; t += gridDim.x) {
        const int m0 = t * 128;

        // A tile: fp32 -> bf16 hi/lo split (4 threads per row)
        {
            int r = tid >> 2;
            int c0 = (tid & 3) * 32;
            char* phi = sm + SM_AHI + r * RS + c0 * 2;
            char* plo = sm + SM_ALO + r * RS + c0 * 2;
            int gr = m0 + r;
            if (gr < M) {
                const float4* ap = (const float4*)(A + (size_t)gr * 128 + c0);
#pragma unroll
                for (int j = 0; j < 8; j++) {
                    float4 v = ap[j];
                    cvt_pair(v.x, v.y, phi + j * 8,     plo + j * 8);
                    cvt_pair(v.z, v.w, phi + j * 8 + 4, plo + j * 8 + 4);
                }
            } else {
#pragma unroll
                for (int j = 0; j < 4; j++) {
                    *(float4*)(phi + j * 16) = make_float4(0.f, 0.f, 0.f, 0.f);
                    *(float4*)(plo + j * 16) = make_float4(0.f, 0.f, 0.f, 0.f);
                }
            }
        }
        __syncthreads();

        float acc[4][4][4];
#pragma unroll
        for (int mt = 0; mt < 4; mt++)
#pragma unroll
            for (int nt = 0; nt < 4; nt++)
#pragma unroll
                for (int j = 0; j < 4; j++) acc[mt][nt][j] = 0.f;

#pragma unroll
        for (int ks = 0; ks < 8; ks++) {
            const uint32_t koff = (uint32_t)ks * 32u;
            uint32_t ahi[4][4], bf[4][4];
#pragma unroll
            for (int mt = 0; mt < 4; mt++)
                LDSM_X4(ahi[mt][0], ahi[mt][1], ahi[mt][2], ahi[mt][3],
                        a_addr0 + (uint32_t)(mt * 16) * RS + koff);
#pragma unroll
            for (int nt = 0; nt < 4; nt++)
                LDSM_X4(bf[nt][0], bf[nt][1], bf[nt][2], bf[nt][3],
                        b_addr0 + (uint32_t)(nt * 8) * RS + koff);
#pragma unroll
            for (int mt = 0; mt < 4; mt++)
#pragma unroll
                for (int nt = 0; nt < 4; nt++) {
                    mma16816(acc[mt][nt], ahi[mt], &bf[nt][0]);  // hh
                    mma16816(acc[mt][nt], ahi[mt], &bf[nt][2]);  // hl
                }
            uint32_t alo[4][4];
#pragma unroll
            for (int mt = 0; mt < 4; mt++)
                LDSM_X4(alo[mt][0], alo[mt][1], alo[mt][2], alo[mt][3],
                        a_addr0 + (SM_ALO - SM_AHI) + (uint32_t)(mt * 16) * RS + koff);
#pragma unroll
            for (int mt = 0; mt < 4; mt++)
#pragma unroll
                for (int nt = 0; nt < 4; nt++)
                    mma16816(acc[mt][nt], alo[mt], &bf[nt][0]);  // lh
        }
        __syncthreads();   // all A-smem reads complete before next tile's store

        // Epilogue (registers + gmem only)
        float* baseo = isRes ? outR : outM;
#pragma unroll
        for (int mt = 0; mt < 4; mt++) {
            int row0 = m0 + wm * 64 + mt * 16 + (lane >> 2);
#pragma unroll
            for (int nt = 0; nt < 4; nt++) {
                int col = colb + nt * 8 + (lane & 3) * 2;
                float v0 = acc[mt][nt][0], v1 = acc[mt][nt][1];
                float v2 = acc[mt][nt][2], v3 = acc[mt][nt][3];
                if (isRes) {
                    v0 = fmaxf(v0 + q0[nt], 0.f); v1 = fmaxf(v1 + q1[nt], 0.f);
                    v2 = fmaxf(v2 + q0[nt], 0.f); v3 = fmaxf(v3 + q1[nt], 0.f);
                }
                if (row0 < M)
                    *(float2*)(baseo + (size_t)row0 * 128 + col) = make_float2(v0, v1);
                if (row0 + 8 < M)
                    *(float2*)(baseo + (size_t)(row0 + 8) * 128 + col) = make_float2(v2, v3);
            }
        }
    }
}

// ---------------------------------------------------------------------------
// CSR build: histogram -> scan1 (block sums) -> scan3 (prefix w/ inline
// bsum reduction) -> fill.  hist/fill at 592 blocks (grid-stride) to avoid
// the same L1tex/atomic queue contention seen in the gather.
// ---------------------------------------------------------------------------
__global__ void hist_kernel(const int* __restrict__ dst, int* __restrict__ deg, int E)
{
    for (int i = blockIdx.x * blockDim.x + threadIdx.x; i < E;
         i += gridDim.x * blockDim.x)
        atomicAdd(&deg[dst[i]], 1);
}

__global__ void scan1_kernel(const int* __restrict__ deg, int* __restrict__ rowptr,
                             int* __restrict__ bsum, int N)
{
    __shared__ int ws[8];
    int tid = threadIdx.x;
    int base = blockIdx.x * 2048 + tid * 8;
    int v[8];
    int run = 0;
#pragma unroll
    for (int i = 0; i < 8; i++) {
        int t = (base + i < N) ? deg[base + i] : 0;
        v[i] = run;
        run += t;
    }
    int lane = tid & 31, wid = tid >> 5;
    int x = run;
#pragma unroll
    for (int o = 1; o < 32; o <<= 1) {
        int y = __shfl_up_sync(0xffffffffu, x, o);
        if (lane >= o) x += y;
    }
    if (lane == 31) ws[wid] = x;
    __syncthreads();
    if (tid == 0) {
        int acc = 0;
#pragma unroll
        for (int j = 0; j < 8; j++) { int t = ws[j]; ws[j] = acc; acc += t; }
        bsum[blockIdx.x] = acc;   // raw block sum
    }
    __syncthreads();
    int excl = x - run + ws[wid];
#pragma unroll
    for (int i = 0; i < 8; i++)
        if (base + i < N) rowptr[base + i] = excl + v[i];
}

__global__ void scan3_kernel(int* __restrict__ rowptr, int* __restrict__ cursor,
                             const int* __restrict__ bsum, int N, int E)
{
    __shared__ int s_off;
    int tid = threadIdx.x;
    if (tid < 32) {
        int acc = 0;
        for (int b = tid; b < blockIdx.x; b += 32) acc += bsum[b];
#pragma unroll
        for (int o = 16; o > 0; o >>= 1)
            acc += __shfl_down_sync(0xffffffffu, acc, o);
        if (tid == 0) s_off = acc;
    }
    __syncthreads();
    int off = s_off;
    int base = blockIdx.x * 2048 + tid * 8;
#pragma unroll
    for (int k = 0; k < 8; k++) {
        int idx = base + k;
        if (idx < N) {
            int r = rowptr[idx] + off;
            rowptr[idx] = r;
            cursor[idx] = r;
        }
    }
    if (blockIdx.x == 0 && tid == 0) rowptr[N] = E;
}

__global__ void fill_kernel(const int* __restrict__ src, const int* __restrict__ dst,
                            int* __restrict__ cursor, int* __restrict__ esrc, int E)
{
    for (int i = blockIdx.x * blockDim.x + threadIdx.x; i < E;
         i += gridDim.x * blockDim.x) {
        int p = atomicAdd(&cursor[dst[i]], 1);
        esrc[p] = src[i];
    }
}

// ---------------------------------------------------------------------------
// Fused gather + combine + stats (oe=4, warp-staged indices, f32x2 accum)
// ---------------------------------------------------------------------------
__global__ __launch_bounds__(256) void gather_combine_kernel(
    const float* __restrict__ m, const float* __restrict__ res,
    const float* __restrict__ bias, const float* __restrict__ c0,
    const int* __restrict__ rowptr, const int* __restrict__ esrc,
    float* __restrict__ out, float* __restrict__ stats, int M)
{
    const int lane = threadIdx.x & 31;
    const int wid  = threadIdx.x >> 5;
    const int nwarps = (gridDim.x * blockDim.x) >> 5;
    const int w0 = (blockIdx.x * blockDim.x + threadIdx.x) >> 5;

    float4 b4 = ((const float4*)bias)[lane];
    float4 c04 = make_float4(0.f, 0.f, 0.f, 0.f);
    if (c0) c04 = ((const float4*)c0)[lane];

    float4 s = make_float4(0.f, 0.f, 0.f, 0.f);
    float4 q = make_float4(0.f, 0.f, 0.f, 0.f);

    for (int node = w0; node < M; node += nwarps) {
        int start = rowptr[node], end = rowptr[node + 1];
        unsigned long long acc0a, acc0b, acc1a, acc1b;
        float2 z2 = make_float2(0.f, 0.f);
        acc0a = *(unsigned long long*)&z2;
        acc0b = acc0a; acc1a = acc0a; acc1b = acc0a;

        for (int base = start; base < end; base += 32) {
            int cnt = end - base;
            if (cnt > 32) cnt = 32;
            int myidx = (lane < cnt) ? __ldg(esrc + base + lane) : 0;
            int j = 0;
            for (; j + 1 < cnt; j += 2) {
                int s0 = __shfl_sync(0xffffffffu, myidx, j);
                int s1 = __shfl_sync(0xffffffffu, myidx, j + 1);
                float4 v0 = ((const float4*)(m + (size_t)s0 * 128))[lane];
                float4 v1 = ((const float4*)(m + (size_t)s1 * 128))[lane];
                const unsigned long long* p0 = (const unsigned long long*)&v0;
                const unsigned long long* p1 = (const unsigned long long*)&v1;
                addf32x2(acc0a, p0[0]); addf32x2(acc0b, p0[1]);
                addf32x2(acc1a, p1[0]); addf32x2(acc1b, p1[1]);
            }
            if (j < cnt) {
                int s0 = __shfl_sync(0xffffffffu, myidx, j);
                float4 v0 = ((const float4*)(m + (size_t)s0 * 128))[lane];
                const unsigned long long* p0 = (const unsigned long long*)&v0;
                addf32x2(acc0a, p0[0]); addf32x2(acc0b, p0[1]);
            }
        }

        float2 a0xy = *(float2*)&acc0a, a0zw = *(float2*)&acc0b;
        float2 a1xy = *(float2*)&acc1a, a1zw = *(float2*)&acc1b;

        float deg = (float)(end - start);
        float4 rr = ((const float4*)(res + (size_t)node * 128))[lane];
        float4 v;
        v.x = fmaxf(a0xy.x + a1xy.x + b4.x + deg * c04.x, 0.f) + rr.x;
        v.y = fmaxf(a0xy.y + a1xy.y + b4.y + deg * c04.y, 0.f) + rr.y;
        v.z = fmaxf(a0zw.x + a1zw.x + b4.z + deg * c04.z, 0.f) + rr.z;
        v.w = fmaxf(a0zw.y + a1zw.y + b4.w + deg * c04.w, 0.f) + rr.w;
        ((float4*)(out + (size_t)node * 128))[lane] = v;
        s.x += v.x; s.y += v.y; s.z += v.z; s.w += v.w;
        q.x += v.x * v.x; q.y += v.y * v.y; q.z += v.z * v.z; q.w += v.w * v.w;
    }

    __shared__ float4 sh[8][32];
    __shared__ float4 shq[8][32];
    sh[wid][lane] = s;
    shq[wid][lane] = q;
    __syncthreads();

    if (wid == 0) {
#pragma unroll
        for (int j = 1; j < 8; j++) {
            float4 t = sh[j][lane];
            s.x += t.x; s.y += t.y; s.z += t.z; s.w += t.w;
            float4 u = shq[j][lane];
            q.x += u.x; q.y += u.y; q.z += u.z; q.w += u.w;
        }
        atomicAdd(&stats[lane * 4 + 0], s.x);
        atomicAdd(&stats[lane * 4 + 1], s.y);
        atomicAdd(&stats[lane * 4 + 2], s.z);
        atomicAdd(&stats[lane * 4 + 3], s.w);
        atomicAdd(&stats[128 + lane * 4 + 0], q.x);
        atomicAdd(&stats[128 + lane * 4 + 1], q.y);
        atomicAdd(&stats[128 + lane * 4 + 2], q.z);
        atomicAdd(&stats[128 + lane * 4 + 3], q.w);
    }
}

// ---------------------------------------------------------------------------
// Normalize with embedded BN finalize
// ---------------------------------------------------------------------------
__global__ __launch_bounds__(256) void normalize_kernel(
    const float* __restrict__ x, const float* __restrict__ stats,
    const float* __restrict__ g, const float* __restrict__ be,
    float invN, float* __restrict__ y, int M)
{
    __shared__ float sc[128], sf[128];
    if (threadIdx.x < 128) {
        int j = threadIdx.x;
        float mu = stats[j] * invN;
        float var = stats[128 + j] * invN - mu * mu;
        float s = rsqrtf(var + 1e-5f) * g[j];
        sc[j] = s;
        sf[j] = be[j] - mu * s;
    }
    __syncthreads();

    int total = M * 32;
    for (int idx = blockIdx.x * blockDim.x + threadIdx.x; idx < total;
         idx += gridDim.x * blockDim.x) {
        int c4 = idx & 31;
        float4 s4 = ((const float4*)sc)[c4];
        float4 f4 = ((const float4*)sf)[c4];
        float4 v = ((const float4*)x)[idx];
        v.x = v.x * s4.x + f4.x;
        v.y = v.y * s4.y + f4.y;
        v.z = v.z * s4.z + f4.z;
        v.w = v.w * s4.w + f4.w;
        ((float4*)y)[idx] = v;
    }
}

// ---------------------------------------------------------------------------
extern "C" void kernel_launch(void* const* d_in, const int* in_sizes, int n_in,
                              void* d_out, int out_size)
{
    const float* h   = (const float*)d_in[0];
    const int*   src = (const int*)d_in[1];
    const int*   dst = (const int*)d_in[2];
    const float* W0  = (const float*)d_in[3];
    const float* b0  = (const float*)d_in[4];
    const float* Wr0 = (const float*)d_in[5];
    const float* br0 = (const float*)d_in[6];
    const float* g0  = (const float*)d_in[7];
    const float* be0 = (const float*)d_in[8];
    const float* W1  = (const float*)d_in[9];
    const float* b1  = (const float*)d_in[10];
    const float* Wr1 = (const float*)d_in[11];
    const float* br1 = (const float*)d_in[12];
    const float* g1  = (const float*)d_in[13];
    const float* be1 = (const float*)d_in[14];

    const int M = in_sizes[0] / 128;
    const int E = in_sizes[1];

    float *A, *B, *C, *Dd, *stats, *c0, *br1p;
    __nv_bfloat16* wimg;
    int *rowptr, *cursor, *esrc, *bsum;
    cudaGetSymbolAddress((void**)&A,      g_bufA);
    cudaGetSymbolAddress((void**)&B,      g_bufB);
    cudaGetSymbolAddress((void**)&C,      g_bufC);
    cudaGetSymbolAddress((void**)&Dd,     g_bufD);
    cudaGetSymbolAddress((void**)&stats,  g_stats);
    cudaGetSymbolAddress((void**)&c0,     g_c0);
    cudaGetSymbolAddress((void**)&br1p,   g_br1p);
    cudaGetSymbolAddress((void**)&rowptr, g_rowptr);
    cudaGetSymbolAddress((void**)&cursor, g_cursor);
    cudaGetSymbolAddress((void**)&esrc,   g_esrc);
    cudaGetSymbolAddress((void**)&bsum,   g_bsum);
    cudaGetSymbolAddress((void**)&wimg,   g_wimg);

    cudaFuncSetAttribute(gemm_pair_kernel,
                         cudaFuncAttributeMaxDynamicSharedMemorySize, SMEM_GP);

    // Side stream + events: created lazily on the FIRST (uncaptured) call.
    static cudaStream_t s2 = nullptr;
    static cudaEvent_t evFork = nullptr, evJoin = nullptr;
    if (!s2) {
        cudaStreamCreateWithFlags(&s2, cudaStreamNonBlocking);
        cudaEventCreateWithFlags(&evFork, cudaEventDisableTiming);
        cudaEventCreateWithFlags(&evJoin, cudaEventDisableTiming);
    }

    const int nb = (M + 2047) / 2048;
    const int nTiles = (M + 127) / 128;
    const int pBlocks = 148;          // persistent: 1 CTA per SM
    const int gcBlocks = 592;         // oe=4 (confirmed optimum)
    const int eBlocks = 592;          // hist/fill: same contention physics
    const float invN = 1.0f / (float)M;
    float* out = (float*)d_out;

    // ---- Fork: CSR build on s2, concurrent with layer-1 GEMM chain ----
    cudaEventRecord(evFork, 0);
    cudaStreamWaitEvent(s2, evFork, 0);
    cudaMemsetAsync(cursor, 0, (size_t)M * sizeof(int), s2);
    hist_kernel<<<eBlocks, 256, 0, s2>>>(dst, cursor, E);
    scan1_kernel<<<nb, 256, 0, s2>>>(cursor, rowptr, bsum, M);
    scan3_kernel<<<nb, 256, 0, s2>>>(rowptr, cursor, bsum, M, E);
    fill_kernel<<<eBlocks, 256, 0, s2>>>(src, dst, cursor, esrc, E);
    cudaEventRecord(evJoin, s2);

    // ---- Main stream: layer-1 weight prep + persistent GEMM pair ----
    prep_pair_kernel<<<256, 128>>>(W0, Wr0, wimg + 0 * 32768, wimg + 1 * 32768);
    gemm_pair_kernel<<<pBlocks, 512, SMEM_GP>>>(h, wimg + 0 * 32768,
                                                wimg + 1 * 32768, br0, A, B,
                                                stats, M, nTiles);

    // ---- Join: gather needs both CSR and (A, B) ----
    cudaStreamWaitEvent(0, evJoin, 0);
    gather_combine_kernel<<<gcBlocks, 256>>>(A, B, b0, nullptr, rowptr, esrc,
                                             C, stats, M);

    // ---- Layer-2 prep (BN fold) ----
    l2prep_kernel<<<258, 128>>>(stats, g0, be0, invN, W1, Wr1, br1,
                                wimg + 2 * 32768, wimg + 3 * 32768, c0, br1p);

    // ---- Layer 2 ----
    gemm_pair_kernel<<<pBlocks, 512, SMEM_GP>>>(C, wimg + 2 * 32768,
                                                wimg + 3 * 32768, br1p, A, B,
                                                stats, M, nTiles);
    gather_combine_kernel<<<gcBlocks, 256>>>(A, B, b1, c0, rowptr, esrc,
                                             Dd, stats, M);
    normalize_kernel<<<1024, 256>>>(Dd, stats, g1, be1, invN, out, M);
}

// round 14
// speedup vs baseline: 1.0628x; 1.0628x over previous
#include <cuda_runtime.h>
#include <cuda_bf16.h>
#include <cstdint>
#include <cstddef>

#define NODES_MAX 100000
#define EDGES_MAX 1600000
#define DD 128

// ---------------------------------------------------------------------------
// Static device scratch
// ---------------------------------------------------------------------------
__device__ float g_bufA[(size_t)NODES_MAX * DD];   // m (x @ W)
__device__ float g_bufB[(size_t)NODES_MAX * DD];   // res
__device__ float g_bufC[(size_t)NODES_MAX * DD];   // y1
__device__ float g_bufD[(size_t)NODES_MAX * DD];   // y2 (pre-norm)
__device__ float g_stats[2 * DD];
__device__ float g_c0[DD];
__device__ float g_br1p[DD];
__device__ int   g_rowptr[NODES_MAX + 1];
__device__ int   g_cursor[NODES_MAX];   // deg histogram, then fill cursor
__device__ int   g_esrc[EDGES_MAX];
__device__ int   g_bsum[128];
__device__ int   g_sync;                // grid-sync counter for fused gather+norm
// 4 weight images (W0, Wr0, W1p, Wr1p): transposed [n][k] bf16, hi then lo
__device__ __nv_bfloat16 g_wimg[4][32768];

// ---------------------------------------------------------------------------
// mma.sync / ldmatrix helpers (target-portable PTX, no 'a'-suffix features)
// ---------------------------------------------------------------------------
__device__ __forceinline__ uint32_t smem_to_u32(const void* p) {
    uint32_t a;
    asm("{ .reg .u64 t; cvta.to.shared.u64 t, %1; cvt.u32.u64 %0, t; }"
        : "=r"(a) : "l"(p));
    return a;
}

#define LDSM_X4(r0, r1, r2, r3, addr) \
    asm volatile("ldmatrix.sync.aligned.m8n8.x4.shared.b16 {%0,%1,%2,%3}, [%4];" \
                 : "=r"(r0), "=r"(r1), "=r"(r2), "=r"(r3) : "r"(addr))
#define LDSM_X2(r0, r1, addr) \
    asm volatile("ldmatrix.sync.aligned.m8n8.x2.shared.b16 {%0,%1}, [%2];" \
                 : "=r"(r0), "=r"(r1) : "r"(addr))

__device__ __forceinline__ void mma16816(float* c, const uint32_t* a,
                                         const uint32_t* b) {
    asm volatile(
        "mma.sync.aligned.m16n8k16.row.col.f32.bf16.bf16.f32 "
        "{%0,%1,%2,%3}, {%4,%5,%6,%7}, {%8,%9}, {%0,%1,%2,%3};"
        : "+f"(c[0]), "+f"(c[1]), "+f"(c[2]), "+f"(c[3])
        : "r"(a[0]), "r"(a[1]), "r"(a[2]), "r"(a[3]), "r"(b[0]), "r"(b[1]));
}

// packed fp32 pair add (proven on this toolchain since R2)
__device__ __forceinline__ void addf32x2(unsigned long long& d,
                                         unsigned long long a) {
    asm("add.rn.f32x2 %0, %0, %1;" : "+l"(d) : "l"(a));
}

__device__ __forceinline__ void split_store(__nv_bfloat16* img, int n, int k, float w)
{
    __nv_bfloat16 hi = __float2bfloat16_rn(w);
    img[n * 128 + k] = hi;
    img[16384 + n * 128 + k] = __float2bfloat16_rn(w - __bfloat162float(hi));
}

// ---------------------------------------------------------------------------
// Layer-1 weight prep: both W0 and Wr0 in one launch (grid 256)
// ---------------------------------------------------------------------------
__global__ void prep_pair_kernel(const float* __restrict__ Wa,
                                 const float* __restrict__ Wb,
                                 __nv_bfloat16* __restrict__ imga,
                                 __nv_bfloat16* __restrict__ imgb)
{
    int b = blockIdx.x;
    const float* W = (b < 128) ? Wa : Wb;
    __nv_bfloat16* img = (b < 128) ? imga : imgb;
    int n = b & 127;
    int k = threadIdx.x;
    split_store(img, n, k, W[k * 128 + n]);
}

// ---------------------------------------------------------------------------
// Layer-2 prep megakernel (BN fold into weights/biases), grid 258 x 128
// ---------------------------------------------------------------------------
__global__ void l2prep_kernel(const float* __restrict__ stats,
                              const float* __restrict__ g,
                              const float* __restrict__ be,
                              float invN,
                              const float* __restrict__ W1,
                              const float* __restrict__ Wr1,
                              const float* __restrict__ br1,
                              __nv_bfloat16* __restrict__ img2,
                              __nv_bfloat16* __restrict__ img3,
                              float* __restrict__ c0,
                              float* __restrict__ br1p)
{
    int b = blockIdx.x;
    int t = threadIdx.x;
    float mu = stats[t] * invN;
    float var = stats[128 + t] * invN - mu * mu;
    float sc = rsqrtf(var + 1e-5f) * g[t];
    float sf = be[t] - mu * sc;

    if (b < 256) {
        const float* W = (b < 128) ? W1 : Wr1;
        __nv_bfloat16* img = (b < 128) ? img2 : img3;
        int n = b & 127;
        split_store(img, n, t, W[t * 128 + n] * sc);
    } else {
        __shared__ float sh[128];
        sh[t] = sf;
        __syncthreads();
        const float* W = (b == 256) ? W1 : Wr1;
        float s = (b == 256) ? 0.f : br1[t];
        for (int k = 0; k < 128; k++) s += sh[k] * W[k * 128 + t];
        if (b == 256) c0[t] = s;
        else          br1p[t] = s;
    }
}

// ---------------------------------------------------------------------------
// PERSISTENT fused GEMM pair via mma.sync bf16 3-term split (R12-proven):
//   outM = A @ W ; outR = relu(A @ Wr + br)
// grid = 148 (1 CTA/SM), B tiles loaded ONCE per CTA, loop over row tiles.
// Block 0 also zeroes stats + grid-sync counter for the following gather.
// ---------------------------------------------------------------------------
#define RS      272u
#define SM_AHI  0u
#define SM_ALO  34816u
#define SM_BHI  69632u
#define SM_BLO  139264u
#define SMEM_GP 208896u

__device__ __forceinline__ void cvt_pair(float a, float b, char* phi, char* plo)
{
    __nv_bfloat16 ha = __float2bfloat16_rn(a);
    __nv_bfloat16 hb = __float2bfloat16_rn(b);
    *(__nv_bfloat162*)phi = __halves2bfloat162(ha, hb);
    *(__nv_bfloat162*)plo = __halves2bfloat162(
        __float2bfloat16_rn(a - __bfloat162float(ha)),
        __float2bfloat16_rn(b - __bfloat162float(hb)));
}

__global__ __launch_bounds__(512, 1) void gemm_pair_kernel(
    const float* __restrict__ A,
    const __nv_bfloat16* __restrict__ imgW,
    const __nv_bfloat16* __restrict__ imgR,
    const float* __restrict__ br,
    float* __restrict__ outM, float* __restrict__ outR,
    float* __restrict__ stats, int* __restrict__ sync,
    int M, int nTiles)
{
    extern __shared__ char sm[];
    const uint32_t smb = smem_to_u32(sm);
    const int tid = threadIdx.x;
    const int warp = tid >> 5;
    const int lane = tid & 31;

    if (blockIdx.x == 0) {
        if (tid < 256) stats[tid] = 0.f;
        if (tid == 256) *sync = 0;
    }

    // ---- B tiles: load ONCE (rows 0-127: W^T, 128-255: Wr^T) ----
    for (int i = tid; i < 4096; i += 512) {
        int row = i >> 4, q = i & 15;
        const __nv_bfloat16* srcb = (row < 128) ? imgW : imgR;
        int r = row & 127;
        uint4 vhi = ((const uint4*)(srcb + r * 128))[q];
        uint4 vlo = ((const uint4*)(srcb + 16384 + r * 128))[q];
        *(uint4*)(sm + SM_BHI + row * RS + q * 16) = vhi;
        *(uint4*)(sm + SM_BLO + row * RS + q * 16) = vlo;
    }

    const int wm = warp >> 3;
    const int wn = warp & 7;
    const bool isRes = (wn >= 4);
    const int colb = wn * 32 - (isRes ? 128 : 0);

    const uint32_t a_addr0 = smb + SM_AHI
        + (uint32_t)(wm * 64 + (lane & 15)) * RS + (uint32_t)((lane >> 4) & 1) * 16u;
    const uint32_t b_addr0 = smb + SM_BHI
        + (uint32_t)(wn * 32 + (lane & 7)) * RS + (uint32_t)((lane >> 3) & 1) * 16u;

    // epilogue bias regs (loop-invariant)
    float q0[4], q1[4];
    if (isRes) {
#pragma unroll
        for (int nt = 0; nt < 4; nt++) {
            int col = colb + nt * 8 + (lane & 3) * 2;
            q0[nt] = __ldg(br + col);
            q1[nt] = __ldg(br + col + 1);
        }
    }

    // ---- Persistent loop over row tiles ----
    for (int t = blockIdx.x; t < nTiles; t += gridDim.x) {
        const int m0 = t * 128;

        // A tile: fp32 -> bf16 hi/lo split (4 threads per row)
        {
            int r = tid >> 2;
            int c0 = (tid & 3) * 32;
            char* phi = sm + SM_AHI + r * RS + c0 * 2;
            char* plo = sm + SM_ALO + r * RS + c0 * 2;
            int gr = m0 + r;
            if (gr < M) {
                const float4* ap = (const float4*)(A + (size_t)gr * 128 + c0);
#pragma unroll
                for (int j = 0; j < 8; j++) {
                    float4 v = ap[j];
                    cvt_pair(v.x, v.y, phi + j * 8,     plo + j * 8);
                    cvt_pair(v.z, v.w, phi + j * 8 + 4, plo + j * 8 + 4);
                }
            } else {
#pragma unroll
                for (int j = 0; j < 4; j++) {
                    *(float4*)(phi + j * 16) = make_float4(0.f, 0.f, 0.f, 0.f);
                    *(float4*)(plo + j * 16) = make_float4(0.f, 0.f, 0.f, 0.f);
                }
            }
        }
        __syncthreads();

        float acc[4][4][4];
#pragma unroll
        for (int mt = 0; mt < 4; mt++)
#pragma unroll
            for (int nt = 0; nt < 4; nt++)
#pragma unroll
                for (int j = 0; j < 4; j++) acc[mt][nt][j] = 0.f;

#pragma unroll
        for (int ks = 0; ks < 8; ks++) {
            const uint32_t koff = (uint32_t)ks * 32u;
            uint32_t ahi[4][4], bhi[4][2], blo[4][2];
#pragma unroll
            for (int mt = 0; mt < 4; mt++)
                LDSM_X4(ahi[mt][0], ahi[mt][1], ahi[mt][2], ahi[mt][3],
                        a_addr0 + (uint32_t)(mt * 16) * RS + koff);
#pragma unroll
            for (int nt = 0; nt < 4; nt++) {
                uint32_t ba = b_addr0 + (uint32_t)(nt * 8) * RS + koff;
                LDSM_X2(bhi[nt][0], bhi[nt][1], ba);
                LDSM_X2(blo[nt][0], blo[nt][1], ba + (SM_BLO - SM_BHI));
            }
#pragma unroll
            for (int mt = 0; mt < 4; mt++)
#pragma unroll
                for (int nt = 0; nt < 4; nt++) {
                    mma16816(acc[mt][nt], ahi[mt], bhi[nt]);
                    mma16816(acc[mt][nt], ahi[mt], blo[nt]);
                }
            uint32_t alo[4][4];
#pragma unroll
            for (int mt = 0; mt < 4; mt++)
                LDSM_X4(alo[mt][0], alo[mt][1], alo[mt][2], alo[mt][3],
                        a_addr0 + (SM_ALO - SM_AHI) + (uint32_t)(mt * 16) * RS + koff);
#pragma unroll
            for (int mt = 0; mt < 4; mt++)
#pragma unroll
                for (int nt = 0; nt < 4; nt++)
                    mma16816(acc[mt][nt], alo[mt], bhi[nt]);
        }
        __syncthreads();   // all A-smem reads complete before next tile's store

        // Epilogue (registers + gmem only)
        float* baseo = isRes ? outR : outM;
#pragma unroll
        for (int mt = 0; mt < 4; mt++) {
            int row0 = m0 + wm * 64 + mt * 16 + (lane >> 2);
#pragma unroll
            for (int nt = 0; nt < 4; nt++) {
                int col = colb + nt * 8 + (lane & 3) * 2;
                float v0 = acc[mt][nt][0], v1 = acc[mt][nt][1];
                float v2 = acc[mt][nt][2], v3 = acc[mt][nt][3];
                if (isRes) {
                    v0 = fmaxf(v0 + q0[nt], 0.f); v1 = fmaxf(v1 + q1[nt], 0.f);
                    v2 = fmaxf(v2 + q0[nt], 0.f); v3 = fmaxf(v3 + q1[nt], 0.f);
                }
                if (row0 < M)
                    *(float2*)(baseo + (size_t)row0 * 128 + col) = make_float2(v0, v1);
                if (row0 + 8 < M)
                    *(float2*)(baseo + (size_t)(row0 + 8) * 128 + col) = make_float2(v2, v3);
            }
        }
    }
}

// ---------------------------------------------------------------------------
// CSR build (R12-proven grids): histogram -> scan1 -> scan3 -> fill
// ---------------------------------------------------------------------------
__global__ void hist_kernel(const int* __restrict__ dst, int* __restrict__ deg, int E)
{
    int i = blockIdx.x * blockDim.x + threadIdx.x;
    if (i < E) atomicAdd(&deg[dst[i]], 1);
}

__global__ void scan1_kernel(const int* __restrict__ deg, int* __restrict__ rowptr,
                             int* __restrict__ bsum, int N)
{
    __shared__ int ws[8];
    int tid = threadIdx.x;
    int base = blockIdx.x * 2048 + tid * 8;
    int v[8];
    int run = 0;
#pragma unroll
    for (int i = 0; i < 8; i++) {
        int t = (base + i < N) ? deg[base + i] : 0;
        v[i] = run;
        run += t;
    }
    int lane = tid & 31, wid = tid >> 5;
    int x = run;
#pragma unroll
    for (int o = 1; o < 32; o <<= 1) {
        int y = __shfl_up_sync(0xffffffffu, x, o);
        if (lane >= o) x += y;
    }
    if (lane == 31) ws[wid] = x;
    __syncthreads();
    if (tid == 0) {
        int acc = 0;
#pragma unroll
        for (int j = 0; j < 8; j++) { int t = ws[j]; ws[j] = acc; acc += t; }
        bsum[blockIdx.x] = acc;
    }
    __syncthreads();
    int excl = x - run + ws[wid];
#pragma unroll
    for (int i = 0; i < 8; i++)
        if (base + i < N) rowptr[base + i] = excl + v[i];
}

__global__ void scan3_kernel(int* __restrict__ rowptr, int* __restrict__ cursor,
                             const int* __restrict__ bsum, int N, int E)
{
    __shared__ int s_off;
    int tid = threadIdx.x;
    if (tid < 32) {
        int acc = 0;
        for (int b = tid; b < blockIdx.x; b += 32) acc += bsum[b];
#pragma unroll
        for (int o = 16; o > 0; o >>= 1)
            acc += __shfl_down_sync(0xffffffffu, acc, o);
        if (tid == 0) s_off = acc;
    }
    __syncthreads();
    int off = s_off;
    int base = blockIdx.x * 2048 + tid * 8;
#pragma unroll
    for (int k = 0; k < 8; k++) {
        int idx = base + k;
        if (idx < N) {
            int r = rowptr[idx] + off;
            rowptr[idx] = r;
            cursor[idx] = r;
        }
    }
    if (blockIdx.x == 0 && tid == 0) rowptr[N] = E;
}

__global__ void fill_kernel(const int* __restrict__ src, const int* __restrict__ dst,
                            int* __restrict__ cursor, int* __restrict__ esrc, int E)
{
    int i = blockIdx.x * blockDim.x + threadIdx.x;
    if (i < E) {
        int p = atomicAdd(&cursor[dst[i]], 1);
        esrc[p] = src[i];
    }
}

// ---------------------------------------------------------------------------
// Gather core (shared by both gather kernels): accumulate node, combine,
// write pre-norm output, accumulate block stats into smem-reduced warp sums.
// ---------------------------------------------------------------------------
__device__ __forceinline__ void gather_body(
    const float* __restrict__ m, const float* __restrict__ res,
    float4 b4, float4 c04,
    const int* __restrict__ rowptr, const int* __restrict__ esrc,
    float* __restrict__ out, float* __restrict__ stats, int M,
    int lane, int wid, int nwarps, int w0)
{
    float4 s = make_float4(0.f, 0.f, 0.f, 0.f);
    float4 q = make_float4(0.f, 0.f, 0.f, 0.f);

    for (int node = w0; node < M; node += nwarps) {
        int start = rowptr[node], end = rowptr[node + 1];
        unsigned long long acc0a, acc0b, acc1a, acc1b;
        float2 z2 = make_float2(0.f, 0.f);
        acc0a = *(unsigned long long*)&z2;
        acc0b = acc0a; acc1a = acc0a; acc1b = acc0a;

        for (int base = start; base < end; base += 32) {
            int cnt = end - base;
            if (cnt > 32) cnt = 32;
            int myidx = (lane < cnt) ? __ldg(esrc + base + lane) : 0;
            int j = 0;
            for (; j + 1 < cnt; j += 2) {
                int s0 = __shfl_sync(0xffffffffu, myidx, j);
                int s1 = __shfl_sync(0xffffffffu, myidx, j + 1);
                float4 v0 = ((const float4*)(m + (size_t)s0 * 128))[lane];
                float4 v1 = ((const float4*)(m + (size_t)s1 * 128))[lane];
                const unsigned long long* p0 = (const unsigned long long*)&v0;
                const unsigned long long* p1 = (const unsigned long long*)&v1;
                addf32x2(acc0a, p0[0]); addf32x2(acc0b, p0[1]);
                addf32x2(acc1a, p1[0]); addf32x2(acc1b, p1[1]);
            }
            if (j < cnt) {
                int s0 = __shfl_sync(0xffffffffu, myidx, j);
                float4 v0 = ((const float4*)(m + (size_t)s0 * 128))[lane];
                const unsigned long long* p0 = (const unsigned long long*)&v0;
                addf32x2(acc0a, p0[0]); addf32x2(acc0b, p0[1]);
            }
        }

        float2 a0xy = *(float2*)&acc0a, a0zw = *(float2*)&acc0b;
        float2 a1xy = *(float2*)&acc1a, a1zw = *(float2*)&acc1b;

        float deg = (float)(end - start);
        float4 rr = ((const float4*)(res + (size_t)node * 128))[lane];
        float4 v;
        v.x = fmaxf(a0xy.x + a1xy.x + b4.x + deg * c04.x, 0.f) + rr.x;
        v.y = fmaxf(a0xy.y + a1xy.y + b4.y + deg * c04.y, 0.f) + rr.y;
        v.z = fmaxf(a0zw.x + a1zw.x + b4.z + deg * c04.z, 0.f) + rr.z;
        v.w = fmaxf(a0zw.y + a1zw.y + b4.w + deg * c04.w, 0.f) + rr.w;
        ((float4*)(out + (size_t)node * 128))[lane] = v;
        s.x += v.x; s.y += v.y; s.z += v.z; s.w += v.w;
        q.x += v.x * v.x; q.y += v.y * v.y; q.z += v.z * v.z; q.w += v.w * v.w;
    }

    __shared__ float4 sh[8][32];
    __shared__ float4 shq[8][32];
    sh[wid][lane] = s;
    shq[wid][lane] = q;
    __syncthreads();

    if (wid == 0) {
#pragma unroll
        for (int j = 1; j < 8; j++) {
            float4 t = sh[j][lane];
            s.x += t.x; s.y += t.y; s.z += t.z; s.w += t.w;
            float4 u = shq[j][lane];
            q.x += u.x; q.y += u.y; q.z += u.z; q.w += u.w;
        }
        atomicAdd(&stats[lane * 4 + 0], s.x);
        atomicAdd(&stats[lane * 4 + 1], s.y);
        atomicAdd(&stats[lane * 4 + 2], s.z);
        atomicAdd(&stats[lane * 4 + 3], s.w);
        atomicAdd(&stats[128 + lane * 4 + 0], q.x);
        atomicAdd(&stats[128 + lane * 4 + 1], q.y);
        atomicAdd(&stats[128 + lane * 4 + 2], q.z);
        atomicAdd(&stats[128 + lane * 4 + 3], q.w);
    }
}

// ---------------------------------------------------------------------------
// Layer-1 gather (stats consumed later by l2prep)
// ---------------------------------------------------------------------------
__global__ __launch_bounds__(256, 4) void gather_combine_kernel(
    const float* __restrict__ m, const float* __restrict__ res,
    const float* __restrict__ bias, const float* __restrict__ c0,
    const int* __restrict__ rowptr, const int* __restrict__ esrc,
    float* __restrict__ out, float* __restrict__ stats, int M)
{
    const int lane = threadIdx.x & 31;
    const int wid  = threadIdx.x >> 5;
    const int nwarps = (gridDim.x * blockDim.x) >> 5;
    const int w0 = (blockIdx.x * blockDim.x + threadIdx.x) >> 5;

    float4 b4 = ((const float4*)bias)[lane];
    float4 c04 = make_float4(0.f, 0.f, 0.f, 0.f);
    if (c0) c04 = ((const float4*)c0)[lane];

    gather_body(m, res, b4, c04, rowptr, esrc, out, stats, M,
                lane, wid, nwarps, w0);
}

// ---------------------------------------------------------------------------
// Layer-2 gather FUSED with BN finalize + normalize via in-kernel grid sync.
// grid MUST be 148*4 = 592 with __launch_bounds__(256,4): all CTAs co-resident
// -> spin on counter is deadlock-free.
// ---------------------------------------------------------------------------
__global__ __launch_bounds__(256, 4) void gather_norm_kernel(
    const float* __restrict__ m, const float* __restrict__ res,
    const float* __restrict__ bias, const float* __restrict__ c0,
    const int* __restrict__ rowptr, const int* __restrict__ esrc,
    float* __restrict__ pre, float* __restrict__ stats,
    const float* __restrict__ g, const float* __restrict__ be,
    float invN, float* __restrict__ outFinal,
    int* __restrict__ sync, int M)
{
    const int lane = threadIdx.x & 31;
    const int wid  = threadIdx.x >> 5;
    const int nwarps = (gridDim.x * blockDim.x) >> 5;
    const int w0 = (blockIdx.x * blockDim.x + threadIdx.x) >> 5;

    float4 b4 = ((const float4*)bias)[lane];
    float4 c04 = ((const float4*)c0)[lane];

    // ---- Phase 1: gather + combine + stats (writes pre-norm to `pre`) ----
    gather_body(m, res, b4, c04, rowptr, esrc, pre, stats, M,
                lane, wid, nwarps, w0);

    // ---- Grid-wide sync: all stats atomics visible ----
    __threadfence();
    __syncthreads();
    if (threadIdx.x == 0) {
        atomicAdd(sync, 1);
        while (*(volatile int*)sync < (int)gridDim.x) { }
    }
    __syncthreads();

    // ---- Phase 2: BN finalize (per block) + normalize pre -> outFinal ----
    __shared__ float sc[128], sf[128];
    if (threadIdx.x < 128) {
        int j = threadIdx.x;
        float mu = stats[j] * invN;
        float var = stats[128 + j] * invN - mu * mu;
        float s = rsqrtf(var + 1e-5f) * g[j];
        sc[j] = s;
        sf[j] = be[j] - mu * s;
    }
    __syncthreads();

    int total = M * 32;
    for (int idx = blockIdx.x * blockDim.x + threadIdx.x; idx < total;
         idx += gridDim.x * blockDim.x) {
        int c4 = idx & 31;
        float4 s4 = ((const float4*)sc)[c4];
        float4 f4 = ((const float4*)sf)[c4];
        float4 v = ((const float4*)pre)[idx];
        v.x = v.x * s4.x + f4.x;
        v.y = v.y * s4.y + f4.y;
        v.z = v.z * s4.z + f4.z;
        v.w = v.w * s4.w + f4.w;
        ((float4*)outFinal)[idx] = v;
    }
}

// ---------------------------------------------------------------------------
extern "C" void kernel_launch(void* const* d_in, const int* in_sizes, int n_in,
                              void* d_out, int out_size)
{
    const float* h   = (const float*)d_in[0];
    const int*   src = (const int*)d_in[1];
    const int*   dst = (const int*)d_in[2];
    const float* W0  = (const float*)d_in[3];
    const float* b0  = (const float*)d_in[4];
    const float* Wr0 = (const float*)d_in[5];
    const float* br0 = (const float*)d_in[6];
    const float* g0  = (const float*)d_in[7];
    const float* be0 = (const float*)d_in[8];
    const float* W1  = (const float*)d_in[9];
    const float* b1  = (const float*)d_in[10];
    const float* Wr1 = (const float*)d_in[11];
    const float* br1 = (const float*)d_in[12];
    const float* g1  = (const float*)d_in[13];
    const float* be1 = (const float*)d_in[14];

    const int M = in_sizes[0] / 128;
    const int E = in_sizes[1];

    float *A, *B, *C, *Dd, *stats, *c0, *br1p;
    __nv_bfloat16* wimg;
    int *rowptr, *cursor, *esrc, *bsum, *syncp;
    cudaGetSymbolAddress((void**)&A,      g_bufA);
    cudaGetSymbolAddress((void**)&B,      g_bufB);
    cudaGetSymbolAddress((void**)&C,      g_bufC);
    cudaGetSymbolAddress((void**)&Dd,     g_bufD);
    cudaGetSymbolAddress((void**)&stats,  g_stats);
    cudaGetSymbolAddress((void**)&c0,     g_c0);
    cudaGetSymbolAddress((void**)&br1p,   g_br1p);
    cudaGetSymbolAddress((void**)&rowptr, g_rowptr);
    cudaGetSymbolAddress((void**)&cursor, g_cursor);
    cudaGetSymbolAddress((void**)&esrc,   g_esrc);
    cudaGetSymbolAddress((void**)&bsum,   g_bsum);
    cudaGetSymbolAddress((void**)&syncp,  g_sync);
    cudaGetSymbolAddress((void**)&wimg,   g_wimg);

    cudaFuncSetAttribute(gemm_pair_kernel,
                         cudaFuncAttributeMaxDynamicSharedMemorySize, SMEM_GP);

    // Side stream + events: created lazily on the FIRST (uncaptured) call.
    static cudaStream_t s2 = nullptr;
    static cudaEvent_t evFork = nullptr, evJoin = nullptr;
    if (!s2) {
        cudaStreamCreateWithFlags(&s2, cudaStreamNonBlocking);
        cudaEventCreateWithFlags(&evFork, cudaEventDisableTiming);
        cudaEventCreateWithFlags(&evJoin, cudaEventDisableTiming);
    }

    const int eBlocks = (E + 255) / 256;   // R12-proven grids for hist/fill
    const int nb = (M + 2047) / 2048;
    const int nTiles = (M + 127) / 128;
    const int pBlocks = 148;               // persistent GEMM: 1 CTA/SM
    const int gcBlocks = 592;              // oe=4 (confirmed optimum); ALSO
                                           // required = 148*4 for grid sync
    const float invN = 1.0f / (float)M;
    float* out = (float*)d_out;

    // ---- Fork: CSR build on s2, concurrent with layer-1 GEMM chain ----
    cudaEventRecord(evFork, 0);
    cudaStreamWaitEvent(s2, evFork, 0);
    cudaMemsetAsync(cursor, 0, (size_t)M * sizeof(int), s2);
    hist_kernel<<<eBlocks, 256, 0, s2>>>(dst, cursor, E);
    scan1_kernel<<<nb, 256, 0, s2>>>(cursor, rowptr, bsum, M);
    scan3_kernel<<<nb, 256, 0, s2>>>(rowptr, cursor, bsum, M, E);
    fill_kernel<<<eBlocks, 256, 0, s2>>>(src, dst, cursor, esrc, E);
    cudaEventRecord(evJoin, s2);

    // ---- Main stream: layer-1 weight prep + persistent GEMM pair ----
    prep_pair_kernel<<<256, 128>>>(W0, Wr0, wimg + 0 * 32768, wimg + 1 * 32768);
    gemm_pair_kernel<<<pBlocks, 512, SMEM_GP>>>(h, wimg + 0 * 32768,
                                                wimg + 1 * 32768, br0, A, B,
                                                stats, syncp, M, nTiles);

    // ---- Join: gather needs both CSR and (A, B) ----
    cudaStreamWaitEvent(0, evJoin, 0);
    gather_combine_kernel<<<gcBlocks, 256>>>(A, B, b0, nullptr, rowptr, esrc,
                                             C, stats, M);

    // ---- Layer-2 prep (BN fold) ----
    l2prep_kernel<<<258, 128>>>(stats, g0, be0, invN, W1, Wr1, br1,
                                wimg + 2 * 32768, wimg + 3 * 32768, c0, br1p);

    // ---- Layer 2: GEMM pair, then FUSED gather+BN+normalize ----
    gemm_pair_kernel<<<pBlocks, 512, SMEM_GP>>>(C, wimg + 2 * 32768,
                                                wimg + 3 * 32768, br1p, A, B,
                                                stats, syncp, M, nTiles);
    gather_norm_kernel<<<gcBlocks, 256>>>(A, B, b1, c0, rowptr, esrc,
                                          Dd, stats, g1, be1, invN, out,
                                          syncp, M);
}